// round 2
// baseline (speedup 1.0000x reference)
#include <cuda_runtime.h>

#define NCOLS            696     // 16 + 120 + 560
#define NQ_TOTAL         174     // NCOLS / 4
#define ROWS_PER_BLOCK   128
#define THREADS          128
#define ROW_STRIDE       68      // 64 data words + 4 pad (conflict-free STS.128 & LDS.128)

// Dubois t-norm for a,b >= 0:  a*b / max(max(a,b), lambda) == min(a, b, a*b/lambda)
__device__ __forceinline__ float tnorm(float a, float b, float inv_l) {
    return fminf(fminf(a, b), a * b * inv_l);
}

// Pack values for columns [LO,HI) of this thread's row into row-major smem buf
// (buf[tid*ROW_STRIDE + (col-LO)]) using STS.128 every 4 columns.
// Fully unrolled; col is compile-time constant so out-of-range work is DCE'd.
template<int LO, int HI>
__device__ __forceinline__ void compute_chunk(const float xv[16], float inv_l,
                                              float* __restrict__ buf, int tid) {
    float4 acc;
    float* rowp = buf + tid * ROW_STRIDE;

    int col = 0;
    #define EMIT(VAL)                                                           \
        do {                                                                    \
            if (col >= LO && col < HI) {                                        \
                int rel = col - LO;                                             \
                if ((rel & 3) == 0) acc.x = (VAL);                              \
                else if ((rel & 3) == 1) acc.y = (VAL);                         \
                else if ((rel & 3) == 2) acc.z = (VAL);                         \
                else {                                                          \
                    acc.w = (VAL);                                              \
                    *reinterpret_cast<float4*>(rowp + (rel - 3)) = acc;         \
                }                                                               \
            }                                                                   \
            col++;                                                              \
        } while (0)

    // singles: cols 0..15
    #pragma unroll
    for (int i = 0; i < 16; i++) EMIT(xv[i]);

    // pairs: cols 16..135, lexicographic (i<j)
    #pragma unroll
    for (int i = 0; i < 16; i++) {
        #pragma unroll
        for (int j = i + 1; j < 16; j++) EMIT(tnorm(xv[i], xv[j], inv_l));
    }

    // triples: cols 136..695, lexicographic (i<j<k), fold T(T(xi,xj), xk)
    #pragma unroll
    for (int i = 0; i < 16; i++) {
        #pragma unroll
        for (int j = i + 1; j < 16; j++) {
            float p = tnorm(xv[i], xv[j], inv_l);   // dead if no k in range
            #pragma unroll
            for (int k = j + 1; k < 16; k++) EMIT(tnorm(p, xv[k], inv_l));
        }
    }
    #undef EMIT
}

// Coalesced writeout of columns [LO,HI) for all 128 rows of this block.
// LDS.128 conflict-free (contiguous 128B per 8-lane phase), STG.128 coalesced.
template<int LO, int HI>
__device__ __forceinline__ void writeout_chunk(const float* __restrict__ buf,
                                               float4* __restrict__ out4,
                                               int row0, int tid) {
    constexpr int NQ = (HI - LO) / 4;   // float4s per row in this chunk (16 or 14)
    #pragma unroll
    for (int it = 0; it < NQ; it++) {
        int idx = it * THREADS + tid;
        int q = idx % NQ;               // quad within chunk (fast-varying with lane)
        int r = idx / NQ;               // row within block
        float4 v = *reinterpret_cast<const float4*>(buf + r * ROW_STRIDE + 4 * q);
        __stcs(&out4[(size_t)(row0 + r) * NQ_TOTAL + (LO / 4) + q], v);
    }
}

__global__ void __launch_bounds__(THREADS, 4)
dubois_kernel(const float* __restrict__ x,
              const float* __restrict__ lambda_,
              float* __restrict__ out) {
    __shared__ float buf[ROWS_PER_BLOCK * ROW_STRIDE];   // 34,816 B

    const int tid  = threadIdx.x;
    const int row0 = blockIdx.x * ROWS_PER_BLOCK;
    const int row  = row0 + tid;

    const float inv_l = 1.0f / __ldg(lambda_);

    // Load this thread's 16 inputs into registers (4x LDG.128).
    float xv[16];
    const float4* xp = reinterpret_cast<const float4*>(x) + (size_t)row * 4;
    float4 a = xp[0], b = xp[1], c = xp[2], d = xp[3];
    xv[0]=a.x;  xv[1]=a.y;  xv[2]=a.z;  xv[3]=a.w;
    xv[4]=b.x;  xv[5]=b.y;  xv[6]=b.z;  xv[7]=b.w;
    xv[8]=c.x;  xv[9]=c.y;  xv[10]=c.z; xv[11]=c.w;
    xv[12]=d.x; xv[13]=d.y; xv[14]=d.z; xv[15]=d.w;

    float4* out4 = reinterpret_cast<float4*>(out);

#define DUBOIS_CHUNK(LO, HI)                            \
    compute_chunk<LO, HI>(xv, inv_l, buf, tid);         \
    __syncthreads();                                    \
    writeout_chunk<LO, HI>(buf, out4, row0, tid);       \
    __syncthreads();

    DUBOIS_CHUNK(0,   64)
    DUBOIS_CHUNK(64,  128)
    DUBOIS_CHUNK(128, 192)
    DUBOIS_CHUNK(192, 256)
    DUBOIS_CHUNK(256, 320)
    DUBOIS_CHUNK(320, 384)
    DUBOIS_CHUNK(384, 448)
    DUBOIS_CHUNK(448, 512)
    DUBOIS_CHUNK(512, 576)
    DUBOIS_CHUNK(576, 640)
    DUBOIS_CHUNK(640, 696)

#undef DUBOIS_CHUNK
}

extern "C" void kernel_launch(void* const* d_in, const int* in_sizes, int n_in,
                              void* d_out, int out_size) {
    const float* x   = (const float*)d_in[0];
    const float* lam = (const float*)d_in[1];
    float* out = (float*)d_out;

    int rows = in_sizes[0] / 16;                 // 131072
    int grid = rows / ROWS_PER_BLOCK;            // 1024
    dubois_kernel<<<grid, THREADS>>>(x, lam, out);
}

// round 3
// speedup vs baseline: 1.3326x; 1.3326x over previous
#include <cuda_runtime.h>

#define NCOLS            696     // 16 + 120 + 560
#define NQ_TOTAL         174     // NCOLS / 4
#define ROWS_PER_BLOCK   128
#define THREADS          128
#define MIN_BLOCKS       3       // <=168 regs: fits live set, no spills; 12 warps/SM
#define ROW_STRIDE       68      // 64 data words + 4 pad (conflict-free STS.128 & LDS.128)

// Dubois t-norm for a,b >= 0:  a*b / max(max(a,b), lambda) == min(a, b, a*b/lambda)
__device__ __forceinline__ float tnorm(float a, float b, float inv_l) {
    return fminf(fminf(a, b), a * b * inv_l);
}

// Pack values for columns [LO,HI) of this thread's row into row-major smem buf
// (buf[tid*ROW_STRIDE + (col-LO)]) using STS.128 every 4 columns.
// col/rel are compile-time constants; the if-chain resolves statically (no branches).
template<int LO, int HI>
__device__ __forceinline__ void compute_chunk(const float xv[16], float inv_l,
                                              float* __restrict__ buf, int tid) {
    float4 acc;
    float* rowp = buf + tid * ROW_STRIDE;

    int col = 0;
    #define EMIT(VAL)                                                           \
        do {                                                                    \
            if (col >= LO && col < HI) {                                        \
                int rel = col - LO;                                             \
                if ((rel & 3) == 0) acc.x = (VAL);                              \
                else if ((rel & 3) == 1) acc.y = (VAL);                         \
                else if ((rel & 3) == 2) acc.z = (VAL);                         \
                else {                                                          \
                    acc.w = (VAL);                                              \
                    *reinterpret_cast<float4*>(rowp + (rel - 3)) = acc;         \
                }                                                               \
            }                                                                   \
            col++;                                                              \
        } while (0)

    // singles: cols 0..15
    #pragma unroll
    for (int i = 0; i < 16; i++) EMIT(xv[i]);

    // pairs: cols 16..135, lexicographic (i<j)
    #pragma unroll
    for (int i = 0; i < 16; i++) {
        #pragma unroll
        for (int j = i + 1; j < 16; j++) EMIT(tnorm(xv[i], xv[j], inv_l));
    }

    // triples: cols 136..695, lexicographic (i<j<k), fold T(T(xi,xj), xk)
    #pragma unroll
    for (int i = 0; i < 16; i++) {
        #pragma unroll
        for (int j = i + 1; j < 16; j++) {
            float p = tnorm(xv[i], xv[j], inv_l);   // dead if no k in range
            #pragma unroll
            for (int k = j + 1; k < 16; k++) EMIT(tnorm(p, xv[k], inv_l));
        }
    }
    #undef EMIT
}

// Coalesced writeout of columns [LO,HI) for all 128 rows of this block.
// LDS.128 conflict-free (contiguous 128B per 8-lane phase), STG.128 coalesced.
template<int LO, int HI>
__device__ __forceinline__ void writeout_chunk(const float* __restrict__ buf,
                                               float4* __restrict__ out4,
                                               int row0, int tid) {
    constexpr int NQ = (HI - LO) / 4;   // float4s per row in this chunk (16 or 14)
    #pragma unroll
    for (int it = 0; it < NQ; it++) {
        int idx = it * THREADS + tid;
        int q = idx % NQ;               // quad within chunk (fast-varying with lane)
        int r = idx / NQ;               // row within block
        float4 v = *reinterpret_cast<const float4*>(buf + r * ROW_STRIDE + 4 * q);
        __stcs(&out4[(size_t)(row0 + r) * NQ_TOTAL + (LO / 4) + q], v);
    }
}

__global__ void __launch_bounds__(THREADS, MIN_BLOCKS)
dubois_kernel(const float* __restrict__ x,
              const float* __restrict__ lambda_,
              float* __restrict__ out) {
    __shared__ float buf[ROWS_PER_BLOCK * ROW_STRIDE];   // 34,816 B

    const int tid  = threadIdx.x;
    const int row0 = blockIdx.x * ROWS_PER_BLOCK;
    const int row  = row0 + tid;

    const float inv_l = 1.0f / __ldg(lambda_);

    // Load this thread's 16 inputs into registers (4x LDG.128).
    float xv[16];
    const float4* xp = reinterpret_cast<const float4*>(x) + (size_t)row * 4;
    float4 a = xp[0], b = xp[1], c = xp[2], d = xp[3];
    xv[0]=a.x;  xv[1]=a.y;  xv[2]=a.z;  xv[3]=a.w;
    xv[4]=b.x;  xv[5]=b.y;  xv[6]=b.z;  xv[7]=b.w;
    xv[8]=c.x;  xv[9]=c.y;  xv[10]=c.z; xv[11]=c.w;
    xv[12]=d.x; xv[13]=d.y; xv[14]=d.z; xv[15]=d.w;

    float4* out4 = reinterpret_cast<float4*>(out);

#define DUBOIS_CHUNK(LO, HI)                            \
    compute_chunk<LO, HI>(xv, inv_l, buf, tid);         \
    __syncthreads();                                    \
    writeout_chunk<LO, HI>(buf, out4, row0, tid);       \
    __syncthreads();

    DUBOIS_CHUNK(0,   64)
    DUBOIS_CHUNK(64,  128)
    DUBOIS_CHUNK(128, 192)
    DUBOIS_CHUNK(192, 256)
    DUBOIS_CHUNK(256, 320)
    DUBOIS_CHUNK(320, 384)
    DUBOIS_CHUNK(384, 448)
    DUBOIS_CHUNK(448, 512)
    DUBOIS_CHUNK(512, 576)
    DUBOIS_CHUNK(576, 640)
    DUBOIS_CHUNK(640, 696)

#undef DUBOIS_CHUNK
}

extern "C" void kernel_launch(void* const* d_in, const int* in_sizes, int n_in,
                              void* d_out, int out_size) {
    const float* x   = (const float*)d_in[0];
    const float* lam = (const float*)d_in[1];
    float* out = (float*)d_out;

    int rows = in_sizes[0] / 16;                 // 131072
    int grid = rows / ROWS_PER_BLOCK;            // 1024
    dubois_kernel<<<grid, THREADS>>>(x, lam, out);
}

// round 4
// speedup vs baseline: 1.3469x; 1.0107x over previous
#include <cuda_runtime.h>

#define NCOLS            696     // 16 + 120 + 560
#define NQ_TOTAL         174     // NCOLS / 4
#define ROWS_PER_WARP    32
#define WARPS_PER_BLOCK  4
#define THREADS          128
#define MIN_BLOCKS       3
#define ROW_STRIDE       68      // 64 data words + 4 pad
#define BUF_FLOATS       (ROWS_PER_WARP * ROW_STRIDE)   // 2176 floats = 8704 B
// per block: 4 warps * 2 buffers * 8704 B = 69,632 B dynamic smem

// Dubois t-norm for a,b >= 0:  a*b / max(max(a,b), lambda) == min(a, b, a*b/lambda)
__device__ __forceinline__ float tnorm(float a, float b, float inv_l) {
    return fminf(fminf(a, b), a * b * inv_l);
}

// Pack values for columns [LO,HI) of this lane's row into its warp buffer row
// (wbuf[lane*ROW_STRIDE + (col-LO)]) using STS.128 every 4 columns.
// col/rel are compile-time constants; out-of-range work is DCE'd.
template<int LO, int HI>
__device__ __forceinline__ void compute_chunk(const float xv[16], float inv_l,
                                              float* __restrict__ wbuf, int lane) {
    float4 acc;
    float* rowp = wbuf + lane * ROW_STRIDE;

    int col = 0;
    #define EMIT(VAL)                                                           \
        do {                                                                    \
            if (col >= LO && col < HI) {                                        \
                int rel = col - LO;                                             \
                if ((rel & 3) == 0) acc.x = (VAL);                              \
                else if ((rel & 3) == 1) acc.y = (VAL);                         \
                else if ((rel & 3) == 2) acc.z = (VAL);                         \
                else {                                                          \
                    acc.w = (VAL);                                              \
                    *reinterpret_cast<float4*>(rowp + (rel - 3)) = acc;         \
                }                                                               \
            }                                                                   \
            col++;                                                              \
        } while (0)

    #pragma unroll
    for (int i = 0; i < 16; i++) EMIT(xv[i]);                    // singles 0..15

    #pragma unroll
    for (int i = 0; i < 16; i++) {                               // pairs 16..135
        #pragma unroll
        for (int j = i + 1; j < 16; j++) EMIT(tnorm(xv[i], xv[j], inv_l));
    }

    #pragma unroll
    for (int i = 0; i < 16; i++) {                               // triples 136..695
        #pragma unroll
        for (int j = i + 1; j < 16; j++) {
            float p = tnorm(xv[i], xv[j], inv_l);                // dead if no k in range
            #pragma unroll
            for (int k = j + 1; k < 16; k++) EMIT(tnorm(p, xv[k], inv_l));
        }
    }
    #undef EMIT
}

// Coalesced writeout of columns [LO,HI) for this warp's 32 rows.
// LDS.128 conflict-free, STG.128 coalesced (256B+ contiguous per phase).
template<int LO, int HI>
__device__ __forceinline__ void writeout_chunk(const float* __restrict__ wbuf,
                                               float4* __restrict__ out4,
                                               int wrow0, int lane) {
    constexpr int NQ = (HI - LO) / 4;   // 16 or 14 float4s per row in this chunk
    #pragma unroll
    for (int it = 0; it < NQ; it++) {
        int idx = it * 32 + lane;
        int q = idx % NQ;               // quad within chunk (fast with lane)
        int r = idx / NQ;               // row within warp's 32 rows
        float4 v = *reinterpret_cast<const float4*>(wbuf + r * ROW_STRIDE + 4 * q);
        __stcs(&out4[(size_t)(wrow0 + r) * NQ_TOTAL + (LO / 4) + q], v);
    }
}

__global__ void __launch_bounds__(THREADS, MIN_BLOCKS)
dubois_kernel(const float* __restrict__ x,
              const float* __restrict__ lambda_,
              float* __restrict__ out) {
    extern __shared__ float smem[];

    const int lane = threadIdx.x & 31;
    const int wid  = threadIdx.x >> 5;
    float* bufA = smem + wid * 2 * BUF_FLOATS;
    float* bufB = bufA + BUF_FLOATS;

    const int wrow0 = blockIdx.x * (ROWS_PER_WARP * WARPS_PER_BLOCK) + wid * ROWS_PER_WARP;
    const int row   = wrow0 + lane;

    const float inv_l = 1.0f / __ldg(lambda_);

    // Load this lane's 16 inputs into registers (4x LDG.128).
    float xv[16];
    const float4* xp = reinterpret_cast<const float4*>(x) + (size_t)row * 4;
    float4 a = xp[0], b = xp[1], c = xp[2], d = xp[3];
    xv[0]=a.x;  xv[1]=a.y;  xv[2]=a.z;  xv[3]=a.w;
    xv[4]=b.x;  xv[5]=b.y;  xv[6]=b.z;  xv[7]=b.w;
    xv[8]=c.x;  xv[9]=c.y;  xv[10]=c.z; xv[11]=c.w;
    xv[12]=d.x; xv[13]=d.y; xv[14]=d.z; xv[15]=d.w;

    float4* out4 = reinterpret_cast<float4*>(out);

    // Software-pipelined, per-warp double buffer:
    //   step s: writeout(chunk s-1) interleaved with compute(chunk s), syncwarp.
    compute_chunk<0, 64>(xv, inv_l, bufA, lane);
    __syncwarp();

#define STEP(PLO, PHI, CLO, CHI, WB, CB)                         \
    writeout_chunk<PLO, PHI>(WB, out4, wrow0, lane);             \
    compute_chunk<CLO, CHI>(xv, inv_l, CB, lane);                \
    __syncwarp();

    STEP(0,   64,  64,  128, bufA, bufB)
    STEP(64,  128, 128, 192, bufB, bufA)
    STEP(128, 192, 192, 256, bufA, bufB)
    STEP(192, 256, 256, 320, bufB, bufA)
    STEP(256, 320, 320, 384, bufA, bufB)
    STEP(320, 384, 384, 448, bufB, bufA)
    STEP(384, 448, 448, 512, bufA, bufB)
    STEP(448, 512, 512, 576, bufB, bufA)
    STEP(512, 576, 576, 640, bufA, bufB)
    STEP(576, 640, 640, 696, bufB, bufA)
#undef STEP

    writeout_chunk<640, 696>(bufA, out4, wrow0, lane);
}

extern "C" void kernel_launch(void* const* d_in, const int* in_sizes, int n_in,
                              void* d_out, int out_size) {
    const float* x   = (const float*)d_in[0];
    const float* lam = (const float*)d_in[1];
    float* out = (float*)d_out;

    const int SMEM_BYTES = WARPS_PER_BLOCK * 2 * BUF_FLOATS * sizeof(float); // 69,632
    cudaFuncSetAttribute(dubois_kernel, cudaFuncAttributeMaxDynamicSharedMemorySize,
                         SMEM_BYTES);

    int rows = in_sizes[0] / 16;                                  // 131072
    int grid = rows / (ROWS_PER_WARP * WARPS_PER_BLOCK);          // 1024
    dubois_kernel<<<grid, THREADS, SMEM_BYTES>>>(x, lam, out);
}